// round 7
// baseline (speedup 1.0000x reference)
#include <cuda_runtime.h>
#include <cuda_bf16.h>
#include <math.h>
#include <stdint.h>

#define NCLS 19
#define MCOMP 5
#define KCOMP 95
#define AF 64
#define LOG2PI_F 1.8378770664093453f
#define HF 256
#define WF 256
#define TPB 128
#define KDIM 128          // [x_hat | x_hat^2]
#define CSTRIDE 12        // B cols per class: [maha*5 | l*5 | mt | pad]
#define NCOLS 240
#define NPAIRS 10
#define ROWB 272          // padded smem row (128 bf16 + 8 pad)
#define GRIDM 296         // 2 CTAs x 148 SMs

typedef uint32_t u32;

// ---------------- device scratch (no allocs allowed) ----------------
__device__ float g_CKp[KCOMP];
__device__ float g_LDR[NCLS];
__device__ __nv_bfloat16 g_B[NCOLS * KDIM];
__device__ float g_blockCe[8192];
__device__ int   g_blockCnt[8192];
__device__ unsigned int g_done;

// ---------------- smem layout (bytes) ----------------
#define A_OFF    0                    // 128 x 272 = 34816 (aliased by exchange)
#define B_OFF    34816                // 240 x 272 = 65280
#define CKP_OFF  100096               // 96 floats
#define LDR_OFF  100480               // 24 floats
#define SMEM_TOTAL 100576

// ---------------- PTX helpers ----------------
__device__ __forceinline__ u32 smem_u32(const void* p) {
    u32 a;
    asm("{ .reg .u64 t; cvta.to.shared.u64 t, %1; cvt.u32.u64 %0, t; }"
        : "=r"(a) : "l"(p));
    return a;
}
#define LDMX4(r, a) \
    asm volatile("ldmatrix.sync.aligned.m8n8.x4.shared.b16 {%0,%1,%2,%3}, [%4];" \
        : "=r"((r)[0]), "=r"((r)[1]), "=r"((r)[2]), "=r"((r)[3]) : "r"(a))
#define LDMX2(r0, r1, a) \
    asm volatile("ldmatrix.sync.aligned.m8n8.x2.shared.b16 {%0,%1}, [%2];" \
        : "=r"(r0), "=r"(r1) : "r"(a))
#define MMA(c, a, b0_, b1_) \
    asm volatile("mma.sync.aligned.m16n8k16.row.col.f32.bf16.bf16.f32 " \
        "{%0,%1,%2,%3}, {%4,%5,%6,%7}, {%8,%9}, {%0,%1,%2,%3};" \
        : "+f"((c)[0]), "+f"((c)[1]), "+f"((c)[2]), "+f"((c)[3]) \
        : "r"((a)[0]), "r"((a)[1]), "r"((a)[2]), "r"((a)[3]), "r"(b0_), "r"(b1_))

__device__ __forceinline__ u32 pkbf(float lo, float hi) {
    return (u32)__bfloat16_as_ushort(__float2bfloat16_rn(lo)) |
           ((u32)__bfloat16_as_ushort(__float2bfloat16_rn(hi)) << 16);
}

// ---------------- prep (fused): constants + B matrix -----------------
__global__ __launch_bounds__(64) void prep_kernel(
        const float* __restrict__ cov,
        const float* __restrict__ mean,
        const float* __restrict__ tmem,
        const float* __restrict__ ct,
        const float* __restrict__ cs) {
    __shared__ float red[64], red2[64];
    const int t = threadIdx.x;
    const int bk = blockIdx.x;
    const __nv_bfloat16 z = __float2bfloat16_rn(0.f);

    if (bk < KCOMP) {
        const int c = bk / 5, j = bk - 5 * c;
        const float s = cov[bk * AF + t];
        const float l = mean[bk * AF + t];
        const float q = 1.0f / (s * s);
        const int n1 = (CSTRIDE * c + j) * KDIM;
        const int n2 = (CSTRIDE * c + 5 + j) * KDIM;
        g_B[n1 + t]      = __float2bfloat16_rn(l * q);
        g_B[n1 + 64 + t] = __float2bfloat16_rn(-0.5f * q);
        g_B[n2 + t]      = __float2bfloat16_rn(l);
        g_B[n2 + 64 + t] = z;
        red [t] = logf(s);
        red2[t] = l * l * q;
        __syncthreads();
        #pragma unroll
        for (int st = 32; st > 0; st >>= 1) {
            if (t < st) { red[t] += red[t + st]; red2[t] += red2[t + st]; }
            __syncthreads();
        }
        if (t == 0)
            g_CKp[bk] = -0.5f * (AF * LOG2PI_F + 2.f * red[0] + red2[0]);
    } else if (bk < KCOMP + NCLS) {
        const int c = bk - KCOMP;
        const float* p = tmem + ((size_t)(c * AF + t)) * 100;
        float s = 0.f;
        for (int i = 0; i < 100; i++) s += p[i];
        s *= 0.01f;
        red[t] = s * s;
        __syncthreads();
        #pragma unroll
        for (int st = 32; st > 0; st >>= 1) {
            if (t < st) red[t] += red[t + st];
            __syncthreads();
        }
        const float n = fmaxf(sqrtf(red[0]), 1e-12f);
        const int n1 = (CSTRIDE * c + 10) * KDIM;
        const int n2 = (CSTRIDE * c + 11) * KDIM;
        g_B[n1 + t]      = __float2bfloat16_rn(s / n);
        g_B[n1 + 64 + t] = z;
        g_B[n2 + t]      = z;
        g_B[n2 + 64 + t] = z;
        if (t == 0) {
            float r = ct[c] / cs[c];
            if (isnan(r)) r = 0.f;
            g_LDR[c] = logf(r);
        }
    } else {
        for (int i = t; i < (NCOLS - 228) * KDIM; i += 64)
            g_B[228 * KDIM + i] = z;
        if (t == 0) g_done = 0;
    }
}

// ---------------- main: persistent 2-tile HMMA GEMM + fused epilogue -
__global__ __launch_bounds__(TPB, 2) void main_kernel(
        const float* __restrict__ feat,
        const int*   __restrict__ mask,
        float* __restrict__ out,
        int ntiles) {
    extern __shared__ char smem[];
    const u32 sb = smem_u32(smem);
    float* sCKp = (float*)(smem + CKP_OFF);
    float* sLDR = (float*)(smem + LDR_OFF);

    const int tid = threadIdx.x;
    const int lane = tid & 31;
    const int w = tid >> 5;

    // ---- one-time: B -> smem (rows padded to 272B)
    for (int i = tid; i < NCOLS * 16; i += TPB) {
        const int row = i >> 4, u = i & 15;
        *(uint4*)(smem + B_OFF + row * ROWB + u * 16) =
            ((const uint4*)g_B)[row * 16 + u];
    }
    if (tid < KCOMP) sCKp[tid] = g_CKp[tid];
    if (tid < NCLS)  sLDR[tid] = g_LDR[tid];
    __syncthreads();

    // ---- ldmatrix lane address bases
    u32 aAddr[2];
    {
        const int rin = (lane & 7) + ((lane >> 3) & 1) * 8;
        const int k16 = (lane >> 4) & 1;
        aAddr[0] = sb + A_OFF + (u32)(32 * w + rin) * ROWB + k16 * 16;
        aAddr[1] = aAddr[0] + 16 * ROWB;
    }
    const u32 bA4 = sb + B_OFF
        + (u32)((lane & 7) + ((lane >> 4) & 1) * 8) * ROWB
        + ((lane >> 3) & 1) * 16;
    const int m15 = lane & 15;
    const u32 bA2 = sb + B_OFF + (u32)(16 + (m15 & 7)) * ROWB
        + ((m15 >> 3) & 1) * 16;

    // exchange buffer aliases this warp's (consumed) A region
    char* dxw = smem + A_OFF + w * (32 * ROWB);
    const int r0 = lane >> 2;
    const int cb = 2 * (lane & 3);

    const int npairs_t = ntiles >> 1;
    for (int tp = blockIdx.x; tp < npairs_t; tp += gridDim.x) {
        int valid[2];
        u32 af[2][2][8][4];

        #pragma unroll 1
        for (int tt = 0; tt < 2; tt++) {
            const int pix = (2 * tp + tt) * TPB + tid;
            const int hw = pix & 65535;
            const int b = pix >> 16;

            // validity: some non-ignore class with count >= 12 in 4x4 block
            const int ww = pix & (WF - 1);
            const int hh = (pix >> 8) & (HF - 1);
            const int* mb = mask + ((size_t)b << 20) + (size_t)(hh << 2) * 1024 + (ww << 2);
            valid[tt] = 0;
            {
                int lab[16];
                #pragma unroll
                for (int r = 0; r < 4; r++) {
                    int4 v4 = *(const int4*)(mb + (size_t)r * 1024);
                    lab[r * 4 + 0] = v4.x; lab[r * 4 + 1] = v4.y;
                    lab[r * 4 + 2] = v4.z; lab[r * 4 + 3] = v4.w;
                }
                #pragma unroll
                for (int i = 0; i < 5; i++) {
                    int cnt = 0;
                    #pragma unroll
                    for (int j = 0; j < 16; j++) cnt += (lab[j] == lab[i]);
                    if (lab[i] != 255 && cnt >= 12) valid[tt] = 1;
                }
            }

            // load feature (coalesced), normalize in fp32
            const float* fbp = feat + ((size_t)b << 22) + hw;
            float x[AF];
            float n0 = 0.f, n1 = 0.f, n2 = 0.f, n3 = 0.f;
            #pragma unroll
            for (int a = 0; a < AF; a += 4) {
                x[a]     = fbp[(size_t)a << 16];
                x[a + 1] = fbp[(size_t)(a + 1) << 16];
                x[a + 2] = fbp[(size_t)(a + 2) << 16];
                x[a + 3] = fbp[(size_t)(a + 3) << 16];
                n0 = fmaf(x[a], x[a], n0);         n1 = fmaf(x[a + 1], x[a + 1], n1);
                n2 = fmaf(x[a + 2], x[a + 2], n2); n3 = fmaf(x[a + 3], x[a + 3], n3);
            }
            const float inv = 1.0f / fmaxf(sqrtf((n0 + n1) + (n2 + n3)), 1e-12f);

            // write A row tid = [x_hat | x_hat^2] bf16 (warp-local region)
            __syncwarp();
            {
                char* arow = smem + A_OFF + (size_t)tid * ROWB;
                #pragma unroll
                for (int i = 0; i < 8; i++) {
                    const int a = i * 8;
                    float e0 = x[a] * inv,     e1 = x[a + 1] * inv;
                    float e2 = x[a + 2] * inv, e3 = x[a + 3] * inv;
                    float e4 = x[a + 4] * inv, e5 = x[a + 5] * inv;
                    float e6 = x[a + 6] * inv, e7 = x[a + 7] * inv;
                    uint4 v0, v1;
                    v0.x = pkbf(e0, e1); v0.y = pkbf(e2, e3);
                    v0.z = pkbf(e4, e5); v0.w = pkbf(e6, e7);
                    v1.x = pkbf(e0 * e0, e1 * e1); v1.y = pkbf(e2 * e2, e3 * e3);
                    v1.z = pkbf(e4 * e4, e5 * e5); v1.w = pkbf(e6 * e6, e7 * e7);
                    ((uint4*)arow)[i] = v0;
                    ((uint4*)arow)[8 + i] = v1;
                }
            }
            __syncwarp();

            // resident A fragments for this tile (warp's 32 rows x K=128)
            #pragma unroll
            for (int mt = 0; mt < 2; mt++)
                #pragma unroll
                for (int ks = 0; ks < 8; ks++)
                    LDMX4(af[tt][mt][ks], aAddr[mt] + ks * 32);
            __syncwarp();   // A region reusable (next tile / exchange)
        }

        // ---- per class-pair: GEMM (B loaded once, 12 MMAs) + epilogues
        float gm[2]   = {-1e30f, -1e30f};
        float Zs[2]   = {0.f, 0.f};
        float glab[2] = {0.f, 0.f};
        float bestL[2] = {-1e30f, -1e30f};

        #pragma unroll 1
        for (int p = 0; p < NPAIRS; p++) {
            float c0[24], c1[24];
            #pragma unroll
            for (int i = 0; i < 24; i++) { c0[i] = 0.f; c1[i] = 0.f; }
            const u32 b4 = bA4 + (u32)p * (24 * ROWB);
            const u32 b2 = bA2 + (u32)p * (24 * ROWB);

            u32 br[4], d0, d1;
            LDMX4(br, b4);
            LDMX2(d0, d1, b2);
            #pragma unroll
            for (int ks = 0; ks < 8; ks++) {
                u32 brn[4], dn0, dn1;
                if (ks < 7) {
                    LDMX4(brn, b4 + (ks + 1) * 32);
                    LDMX2(dn0, dn1, b2 + (ks + 1) * 32);
                }
                MMA(c0 + 0,  af[0][0][ks], br[0], br[1]);
                MMA(c0 + 4,  af[0][1][ks], br[0], br[1]);
                MMA(c1 + 0,  af[1][0][ks], br[0], br[1]);
                MMA(c1 + 4,  af[1][1][ks], br[0], br[1]);
                MMA(c0 + 8,  af[0][0][ks], br[2], br[3]);
                MMA(c0 + 12, af[0][1][ks], br[2], br[3]);
                MMA(c1 + 8,  af[1][0][ks], br[2], br[3]);
                MMA(c1 + 12, af[1][1][ks], br[2], br[3]);
                MMA(c0 + 16, af[0][0][ks], d0, d1);
                MMA(c0 + 20, af[0][1][ks], d0, d1);
                MMA(c1 + 16, af[1][0][ks], d0, d1);
                MMA(c1 + 20, af[1][1][ks], d0, d1);
                if (ks < 7) {
                    br[0] = brn[0]; br[1] = brn[1]; br[2] = brn[2]; br[3] = brn[3];
                    d0 = dn0; d1 = dn1;
                }
            }

            // D exchange: both tiles through warp-local buffer
            __syncwarp();
            #pragma unroll
            for (int mt = 0; mt < 2; mt++)
                #pragma unroll
                for (int nt = 0; nt < 3; nt++) {
                    const float* cc0 = &c0[(nt * 2 + mt) * 4];
                    const float* cc1 = &c1[(nt * 2 + mt) * 4];
                    char* base0 = dxw;
                    char* base1 = dxw + 3328;
                    *(float2*)(base0 + (r0 + mt * 16) * 104 + (nt * 8 + cb) * 4)
                        = make_float2(cc0[0], cc0[1]);
                    *(float2*)(base0 + (r0 + 8 + mt * 16) * 104 + (nt * 8 + cb) * 4)
                        = make_float2(cc0[2], cc0[3]);
                    *(float2*)(base1 + (r0 + mt * 16) * 104 + (nt * 8 + cb) * 4)
                        = make_float2(cc1[0], cc1[1]);
                    *(float2*)(base1 + (r0 + 8 + mt * 16) * 104 + (nt * 8 + cb) * 4)
                        = make_float2(cc1[2], cc1[3]);
                }
            __syncwarp();

            #pragma unroll
            for (int tt = 0; tt < 2; tt++) {
                float v[24];
                const char* rdx = dxw + tt * 3328 + lane * 104;
                #pragma unroll
                for (int i = 0; i < 12; i++) {
                    float2 t2 = *(const float2*)(rdx + i * 8);
                    v[2 * i] = t2.x; v[2 * i + 1] = t2.y;
                }

                #pragma unroll
                for (int cc2 = 0; cc2 < 2; cc2++) {
                    const int c = 2 * p + cc2;
                    if (c < NCLS) {
                        const float* vb = v + cc2 * 12;
                        float lp0 = sCKp[c * 5 + 0] + vb[0];
                        float lp1 = sCKp[c * 5 + 1] + vb[1];
                        float lp2 = sCKp[c * 5 + 2] + vb[2];
                        float lp3 = sCKp[c * 5 + 3] + vb[3];
                        float lp4 = sCKp[c * 5 + 4] + vb[4];
                        float mmax = fmaxf(fmaxf(fmaxf(lp0, lp1), fmaxf(lp2, lp3)), lp4);
                        float msum = __expf(lp0 - mmax) + __expf(lp1 - mmax)
                                   + __expf(lp2 - mmax) + __expf(lp3 - mmax)
                                   + __expf(lp4 - mmax);
                        float lmx = fmaxf(fmaxf(fmaxf(vb[5], vb[6]), fmaxf(vb[7], vb[8])), vb[9]);
                        const float L = sLDR[c] + vb[10] + mmax + __logf(msum);
                        const float g = lmx * 0.01f;
                        if (g > gm[tt]) { Zs[tt] = Zs[tt] * __expf(gm[tt] - g) + 1.f; gm[tt] = g; }
                        else            { Zs[tt] += __expf(g - gm[tt]); }
                        if (L > bestL[tt]) { bestL[tt] = L; glab[tt] = g; }  // first-max
                    }
                }
            }
            __syncwarp();
        }

        #pragma unroll
        for (int tt = 0; tt < 2; tt++) {
            float ce = valid[tt] ? (gm[tt] + __logf(Zs[tt]) - glab[tt]) : 0.f;
            int   vv = valid[tt];
            #pragma unroll
            for (int off = 16; off > 0; off >>= 1) {
                ce += __shfl_xor_sync(0xffffffffu, ce, off);
                vv += __shfl_xor_sync(0xffffffffu, vv, off);
            }
            if (lane == 0) {
                g_blockCe[(2 * tp + tt) * 4 + w]  = ce;
                g_blockCnt[(2 * tp + tt) * 4 + w] = vv;
            }
        }
    }

    // ---- fused finalize: last CTA reduces all per-warp partials
    __shared__ bool isLast;
    __shared__ float sf4[4];
    __shared__ int   si4[4];
    __threadfence();
    __syncthreads();
    if (tid == 0) {
        unsigned int o = atomicAdd(&g_done, 1u);
        isLast = (o == (unsigned int)(gridDim.x - 1));
    }
    __syncthreads();
    if (isLast) {
        __threadfence();
        const int ntot = ntiles * 4;
        float s = 0.f; int c = 0;
        for (int i = tid; i < ntot; i += TPB) {
            s += g_blockCe[i];
            c += g_blockCnt[i];
        }
        #pragma unroll
        for (int off = 16; off > 0; off >>= 1) {
            s += __shfl_xor_sync(0xffffffffu, s, off);
            c += __shfl_xor_sync(0xffffffffu, c, off);
        }
        if (lane == 0) { sf4[w] = s; si4[w] = c; }
        __syncthreads();
        if (tid == 0) {
            const float tot = ((sf4[0] + sf4[1]) + (sf4[2] + sf4[3]));
            const int   cnt = ((si4[0] + si4[1]) + (si4[2] + si4[3]));
            out[0] = tot / fmaxf((float)cnt, 1.0f);
        }
    }
}

// ---------------- launch ----------------
extern "C" void kernel_launch(void* const* d_in, const int* in_sizes, int n_in,
                              void* d_out, int out_size) {
    const float* feat = (const float*)d_in[0];
    const int*   mask = (const int*)d_in[1];
    const float* mean = (const float*)d_in[2];
    const float* cov  = (const float*)d_in[3];
    const float* tmem = (const float*)d_in[4];
    const float* ct   = (const float*)d_in[5];
    const float* cs   = (const float*)d_in[6];

    const int B = in_sizes[0] / (AF * HF * WF);
    const int npix = B * HF * WF;
    const int ntiles = npix / TPB;

    cudaFuncSetAttribute(main_kernel,
                         cudaFuncAttributeMaxDynamicSharedMemorySize, SMEM_TOTAL);

    prep_kernel<<<KCOMP + NCLS + 1, 64>>>(cov, mean, tmem, ct, cs);
    main_kernel<<<GRIDM, TPB, SMEM_TOTAL>>>(feat, mask, (float*)d_out, ntiles);
}

// round 8
// speedup vs baseline: 1.2259x; 1.2259x over previous
#include <cuda_runtime.h>
#include <cuda_bf16.h>
#include <math.h>
#include <stdint.h>

#define NCLS 19
#define MCOMP 5
#define KCOMP 95
#define AF 64
#define LOG2PI_F 1.8378770664093453f
#define HF 256
#define WF 256
#define TPB 384           // 12 warps, 1 CTA/SM
#define NWARP 12
#define KDIM 128          // [x_hat | x_hat^2]
#define CSTRIDE 12        // B cols per class: [maha*5 | l*5 | mt | pad]
#define NCOLS 240
#define NPAIRS 10
#define ROWB 272          // padded smem row (128 bf16 + 8 pad)
#define WREG (32 * ROWB)  // per-warp A region = 8704 B

typedef uint32_t u32;

// ---------------- device scratch (no allocs allowed) ----------------
__device__ float g_CKp[KCOMP];
__device__ float g_LDR[NCLS];
__device__ __nv_bfloat16 g_B[NCOLS * KDIM];
__device__ float g_blockCe[8192];
__device__ int   g_blockCnt[8192];
__device__ unsigned int g_done;
__device__ unsigned int g_chunk;

// ---------------- smem layout (bytes) ----------------
#define A_OFF    0                    // 12 x 8704 = 104448 (aliased by exchange)
#define B_OFF    104448               // 240 x 272 = 65280
#define CKP_OFF  169728               // 96 floats
#define LDR_OFF  170112               // 24 floats
#define SMEM_TOTAL 170240

// ---------------- PTX helpers ----------------
__device__ __forceinline__ u32 smem_u32(const void* p) {
    u32 a;
    asm("{ .reg .u64 t; cvta.to.shared.u64 t, %1; cvt.u32.u64 %0, t; }"
        : "=r"(a) : "l"(p));
    return a;
}
#define LDMX4(r, a) \
    asm volatile("ldmatrix.sync.aligned.m8n8.x4.shared.b16 {%0,%1,%2,%3}, [%4];" \
        : "=r"((r)[0]), "=r"((r)[1]), "=r"((r)[2]), "=r"((r)[3]) : "r"(a))
#define LDMX2(r0, r1, a) \
    asm volatile("ldmatrix.sync.aligned.m8n8.x2.shared.b16 {%0,%1}, [%2];" \
        : "=r"(r0), "=r"(r1) : "r"(a))
#define MMA(c, a, b0_, b1_) \
    asm volatile("mma.sync.aligned.m16n8k16.row.col.f32.bf16.bf16.f32 " \
        "{%0,%1,%2,%3}, {%4,%5,%6,%7}, {%8,%9}, {%0,%1,%2,%3};" \
        : "+f"((c)[0]), "+f"((c)[1]), "+f"((c)[2]), "+f"((c)[3]) \
        : "r"((a)[0]), "r"((a)[1]), "r"((a)[2]), "r"((a)[3]), "r"(b0_), "r"(b1_))

__device__ __forceinline__ u32 pkbf(float lo, float hi) {
    return (u32)__bfloat16_as_ushort(__float2bfloat16_rn(lo)) |
           ((u32)__bfloat16_as_ushort(__float2bfloat16_rn(hi)) << 16);
}

// ---------------- prep (fused): constants + B matrix -----------------
__global__ __launch_bounds__(64) void prep_kernel(
        const float* __restrict__ cov,
        const float* __restrict__ mean,
        const float* __restrict__ tmem,
        const float* __restrict__ ct,
        const float* __restrict__ cs) {
    __shared__ float red[64], red2[64];
    const int t = threadIdx.x;
    const int bk = blockIdx.x;
    const __nv_bfloat16 z = __float2bfloat16_rn(0.f);

    if (bk < KCOMP) {
        const int c = bk / 5, j = bk - 5 * c;
        const float s = cov[bk * AF + t];
        const float l = mean[bk * AF + t];
        const float q = 1.0f / (s * s);
        const int n1 = (CSTRIDE * c + j) * KDIM;
        const int n2 = (CSTRIDE * c + 5 + j) * KDIM;
        g_B[n1 + t]      = __float2bfloat16_rn(l * q);
        g_B[n1 + 64 + t] = __float2bfloat16_rn(-0.5f * q);
        g_B[n2 + t]      = __float2bfloat16_rn(l);
        g_B[n2 + 64 + t] = z;
        red [t] = logf(s);
        red2[t] = l * l * q;
        __syncthreads();
        #pragma unroll
        for (int st = 32; st > 0; st >>= 1) {
            if (t < st) { red[t] += red[t + st]; red2[t] += red2[t + st]; }
            __syncthreads();
        }
        if (t == 0)
            g_CKp[bk] = -0.5f * (AF * LOG2PI_F + 2.f * red[0] + red2[0]);
    } else if (bk < KCOMP + NCLS) {
        const int c = bk - KCOMP;
        const float* p = tmem + ((size_t)(c * AF + t)) * 100;
        float s = 0.f;
        for (int i = 0; i < 100; i++) s += p[i];
        s *= 0.01f;
        red[t] = s * s;
        __syncthreads();
        #pragma unroll
        for (int st = 32; st > 0; st >>= 1) {
            if (t < st) red[t] += red[t + st];
            __syncthreads();
        }
        const float n = fmaxf(sqrtf(red[0]), 1e-12f);
        const int n1 = (CSTRIDE * c + 10) * KDIM;
        const int n2 = (CSTRIDE * c + 11) * KDIM;
        g_B[n1 + t]      = __float2bfloat16_rn(s / n);
        g_B[n1 + 64 + t] = z;
        g_B[n2 + t]      = z;
        g_B[n2 + 64 + t] = z;
        if (t == 0) {
            float r = ct[c] / cs[c];
            if (isnan(r)) r = 0.f;
            g_LDR[c] = logf(r);
        }
    } else {
        for (int i = t; i < (NCOLS - 228) * KDIM; i += 64)
            g_B[228 * KDIM + i] = z;
        if (t == 0) { g_done = 0; g_chunk = 0; }
    }
}

// ---------------- main: warp-independent 32-pixel chunks -------------
__global__ __launch_bounds__(TPB, 1) void main_kernel(
        const float* __restrict__ feat,
        const int*   __restrict__ mask,
        float* __restrict__ out,
        int nchunks) {
    extern __shared__ char smem[];
    const u32 sb = smem_u32(smem);
    float* sCKp = (float*)(smem + CKP_OFF);
    float* sLDR = (float*)(smem + LDR_OFF);

    const int tid = threadIdx.x;
    const int lane = tid & 31;
    const int w = tid >> 5;

    // ---- one-time: B -> smem (rows padded to 272B), single copy
    for (int i = tid; i < NCOLS * 16; i += TPB) {
        const int row = i >> 4, u = i & 15;
        *(uint4*)(smem + B_OFF + row * ROWB + u * 16) =
            ((const uint4*)g_B)[row * 16 + u];
    }
    if (tid < KCOMP) sCKp[tid] = g_CKp[tid];
    if (tid < NCLS)  sLDR[tid] = g_LDR[tid];
    __syncthreads();

    // ---- ldmatrix lane address bases (within this warp's A region)
    const u32 wbase = sb + A_OFF + (u32)w * WREG;
    u32 aAddr[2];
    {
        const int rin = (lane & 7) + ((lane >> 3) & 1) * 8;
        const int k16 = (lane >> 4) & 1;
        aAddr[0] = wbase + (u32)rin * ROWB + k16 * 16;
        aAddr[1] = aAddr[0] + 16 * ROWB;
    }
    const u32 bA4 = sb + B_OFF
        + (u32)((lane & 7) + ((lane >> 4) & 1) * 8) * ROWB
        + ((lane >> 3) & 1) * 16;
    const int m15 = lane & 15;
    const u32 bA2 = sb + B_OFF + (u32)(16 + (m15 & 7)) * ROWB
        + ((m15 >> 3) & 1) * 16;

    // exchange buffer aliases this warp's (consumed) A region
    char* dxw = smem + A_OFF + (size_t)w * WREG;
    const int r0 = lane >> 2;
    const int cb = 2 * (lane & 3);

    // ---- warp-independent dynamic chunk loop
    for (;;) {
        unsigned int ck;
        if (lane == 0) ck = atomicAdd(&g_chunk, 1u);
        ck = __shfl_sync(0xffffffffu, ck, 0);
        if (ck >= (unsigned int)nchunks) break;

        const int pix = (int)ck * 32 + lane;
        const int hw = pix & 65535;
        const int b = pix >> 16;

        // ---- validity: some non-ignore class with count >= 12 in 4x4 block
        const int ww = pix & (WF - 1);
        const int hh = (pix >> 8) & (HF - 1);
        const int* mb = mask + ((size_t)b << 20) + (size_t)(hh << 2) * 1024 + (ww << 2);
        int valid = 0;
        {
            int lab[16];
            #pragma unroll
            for (int r = 0; r < 4; r++) {
                int4 v4 = *(const int4*)(mb + (size_t)r * 1024);
                lab[r * 4 + 0] = v4.x; lab[r * 4 + 1] = v4.y;
                lab[r * 4 + 2] = v4.z; lab[r * 4 + 3] = v4.w;
            }
            #pragma unroll
            for (int i = 0; i < 5; i++) {
                int cnt = 0;
                #pragma unroll
                for (int j = 0; j < 16; j++) cnt += (lab[j] == lab[i]);
                if (lab[i] != 255 && cnt >= 12) valid = 1;
            }
        }

        // ---- load feature (coalesced within warp), normalize in fp32
        const float* fbp = feat + ((size_t)b << 22) + hw;
        float x[AF];
        float n0 = 0.f, n1 = 0.f, n2 = 0.f, n3 = 0.f;
        #pragma unroll
        for (int a = 0; a < AF; a += 4) {
            x[a]     = fbp[(size_t)a << 16];
            x[a + 1] = fbp[(size_t)(a + 1) << 16];
            x[a + 2] = fbp[(size_t)(a + 2) << 16];
            x[a + 3] = fbp[(size_t)(a + 3) << 16];
            n0 = fmaf(x[a], x[a], n0);         n1 = fmaf(x[a + 1], x[a + 1], n1);
            n2 = fmaf(x[a + 2], x[a + 2], n2); n3 = fmaf(x[a + 3], x[a + 3], n3);
        }
        const float inv = 1.0f / fmaxf(sqrtf((n0 + n1) + (n2 + n3)), 1e-12f);

        // ---- write A row lane = [x_hat | x_hat^2] bf16 (warp-local)
        __syncwarp();
        {
            char* arow = smem + A_OFF + (size_t)w * WREG + (size_t)lane * ROWB;
            #pragma unroll
            for (int i = 0; i < 8; i++) {
                const int a = i * 8;
                float e0 = x[a] * inv,     e1 = x[a + 1] * inv;
                float e2 = x[a + 2] * inv, e3 = x[a + 3] * inv;
                float e4 = x[a + 4] * inv, e5 = x[a + 5] * inv;
                float e6 = x[a + 6] * inv, e7 = x[a + 7] * inv;
                uint4 v0, v1;
                v0.x = pkbf(e0, e1); v0.y = pkbf(e2, e3);
                v0.z = pkbf(e4, e5); v0.w = pkbf(e6, e7);
                v1.x = pkbf(e0 * e0, e1 * e1); v1.y = pkbf(e2 * e2, e3 * e3);
                v1.z = pkbf(e4 * e4, e5 * e5); v1.w = pkbf(e6 * e6, e7 * e7);
                ((uint4*)arow)[i] = v0;
                ((uint4*)arow)[8 + i] = v1;
            }
        }
        __syncwarp();

        // ---- resident A fragments (warp's 32 rows x K=128)
        u32 af[2][8][4];
        #pragma unroll
        for (int mt = 0; mt < 2; mt++)
            #pragma unroll
            for (int ks = 0; ks < 8; ks++)
                LDMX4(af[mt][ks], aAddr[mt] + ks * 32);
        __syncwarp();   // A region may now be reused as exchange buffer

        // ---- per class-pair: GEMM (B prefetch pipelined) + exchange + epilogue
        float gm = -1e30f, Z = 0.f, glab = 0.f, bestL = -1e30f;

        #pragma unroll 1
        for (int p = 0; p < NPAIRS; p++) {
            float cacc[24];
            #pragma unroll
            for (int i = 0; i < 24; i++) cacc[i] = 0.f;
            const u32 b4 = bA4 + (u32)p * (24 * ROWB);
            const u32 b2 = bA2 + (u32)p * (24 * ROWB);

            u32 br[4], d0, d1;
            LDMX4(br, b4);
            LDMX2(d0, d1, b2);
            #pragma unroll
            for (int ks = 0; ks < 8; ks++) {
                u32 brn[4], dn0, dn1;
                if (ks < 7) {
                    LDMX4(brn, b4 + (ks + 1) * 32);
                    LDMX2(dn0, dn1, b2 + (ks + 1) * 32);
                }
                MMA(cacc + 0,  af[0][ks], br[0], br[1]);
                MMA(cacc + 4,  af[1][ks], br[0], br[1]);
                MMA(cacc + 8,  af[0][ks], br[2], br[3]);
                MMA(cacc + 12, af[1][ks], br[2], br[3]);
                MMA(cacc + 16, af[0][ks], d0, d1);
                MMA(cacc + 20, af[1][ks], d0, d1);
                if (ks < 7) {
                    br[0] = brn[0]; br[1] = brn[1]; br[2] = brn[2]; br[3] = brn[3];
                    d0 = dn0; d1 = dn1;
                }
            }

            // D exchange through warp-local buffer (rows 26 floats = 104B)
            __syncwarp();
            #pragma unroll
            for (int mt = 0; mt < 2; mt++)
                #pragma unroll
                for (int nt = 0; nt < 3; nt++) {
                    const float* cc = &cacc[(nt * 2 + mt) * 4];
                    *(float2*)(dxw + (r0 + mt * 16) * 104 + (nt * 8 + cb) * 4)
                        = make_float2(cc[0], cc[1]);
                    *(float2*)(dxw + (r0 + 8 + mt * 16) * 104 + (nt * 8 + cb) * 4)
                        = make_float2(cc[2], cc[3]);
                }
            __syncwarp();
            float v[24];
            {
                const char* rdx = dxw + lane * 104;
                #pragma unroll
                for (int i = 0; i < 12; i++) {
                    float2 t2 = *(const float2*)(rdx + i * 8);
                    v[2 * i] = t2.x; v[2 * i + 1] = t2.y;
                }
            }
            __syncwarp();

            // epilogue: two classes of this pair (streaming, ascending c)
            #pragma unroll
            for (int cc2 = 0; cc2 < 2; cc2++) {
                const int c = 2 * p + cc2;
                if (c < NCLS) {
                    const float* vb = v + cc2 * 12;
                    float lp0 = sCKp[c * 5 + 0] + vb[0];
                    float lp1 = sCKp[c * 5 + 1] + vb[1];
                    float lp2 = sCKp[c * 5 + 2] + vb[2];
                    float lp3 = sCKp[c * 5 + 3] + vb[3];
                    float lp4 = sCKp[c * 5 + 4] + vb[4];
                    float mmax = fmaxf(fmaxf(fmaxf(lp0, lp1), fmaxf(lp2, lp3)), lp4);
                    float msum = __expf(lp0 - mmax) + __expf(lp1 - mmax)
                               + __expf(lp2 - mmax) + __expf(lp3 - mmax)
                               + __expf(lp4 - mmax);
                    float lmx = fmaxf(fmaxf(fmaxf(vb[5], vb[6]), fmaxf(vb[7], vb[8])), vb[9]);
                    const float L = sLDR[c] + vb[10] + mmax + __logf(msum);
                    const float g = lmx * 0.01f;
                    if (g > gm) { Z = Z * __expf(gm - g) + 1.f; gm = g; }
                    else        { Z += __expf(g - gm); }
                    if (L > bestL) { bestL = L; glab = g; }   // first-max (strict >)
                }
            }
        }

        float ce = valid ? (gm + __logf(Z) - glab) : 0.f;
        int   vv = valid;

        // deterministic warp butterfly reduction -> per-chunk partial
        #pragma unroll
        for (int off = 16; off > 0; off >>= 1) {
            ce += __shfl_xor_sync(0xffffffffu, ce, off);
            vv += __shfl_xor_sync(0xffffffffu, vv, off);
        }
        if (lane == 0) {
            g_blockCe[ck]  = ce;
            g_blockCnt[ck] = vv;
        }
    }

    // ---- fused finalize: last CTA reduces all per-chunk partials
    __shared__ bool isLast;
    __shared__ float sfw[NWARP];
    __shared__ int   siw[NWARP];
    __threadfence();
    __syncthreads();
    if (tid == 0) {
        unsigned int o = atomicAdd(&g_done, 1u);
        isLast = (o == (unsigned int)(gridDim.x - 1));
    }
    __syncthreads();
    if (isLast) {
        __threadfence();
        float s = 0.f; int c = 0;
        for (int i = tid; i < nchunks; i += TPB) {
            s += g_blockCe[i];
            c += g_blockCnt[i];
        }
        #pragma unroll
        for (int off = 16; off > 0; off >>= 1) {
            s += __shfl_xor_sync(0xffffffffu, s, off);
            c += __shfl_xor_sync(0xffffffffu, c, off);
        }
        if (lane == 0) { sfw[w] = s; siw[w] = c; }
        __syncthreads();
        if (tid == 0) {
            float tot = 0.f; int cnt = 0;
            #pragma unroll
            for (int i = 0; i < NWARP; i++) { tot += sfw[i]; cnt += siw[i]; }
            out[0] = tot / fmaxf((float)cnt, 1.0f);
        }
    }
}

// ---------------- launch ----------------
extern "C" void kernel_launch(void* const* d_in, const int* in_sizes, int n_in,
                              void* d_out, int out_size) {
    const float* feat = (const float*)d_in[0];
    const int*   mask = (const int*)d_in[1];
    const float* mean = (const float*)d_in[2];
    const float* cov  = (const float*)d_in[3];
    const float* tmem = (const float*)d_in[4];
    const float* ct   = (const float*)d_in[5];
    const float* cs   = (const float*)d_in[6];

    const int B = in_sizes[0] / (AF * HF * WF);
    const int npix = B * HF * WF;
    const int nchunks = npix / 32;

    cudaFuncSetAttribute(main_kernel,
                         cudaFuncAttributeMaxDynamicSharedMemorySize, SMEM_TOTAL);

    prep_kernel<<<KCOMP + NCLS + 1, 64>>>(cov, mean, tmem, ct, cs);
    main_kernel<<<148, TPB, SMEM_TOTAL>>>(feat, mask, (float*)d_out, nchunks);
}

// round 9
// speedup vs baseline: 1.2687x; 1.0349x over previous
#include <cuda_runtime.h>
#include <cuda_bf16.h>
#include <math.h>
#include <stdint.h>

#define NCLS 19
#define MCOMP 5
#define KCOMP 95
#define AF 64
#define LOG2PI_F 1.8378770664093453f
#define HF 256
#define WF 256
#define TPB 384           // 12 warps, 1 CTA/SM
#define NWARP 12
#define KDIM 128          // [x_hat | x_hat^2]
#define NCOLS 240         // 5 passes x 48 cols (4 classes per pass, class-per-quad-lane)
#define NSUB 10           // 10 sub-passes of 24 cols (3 n-tiles)
#define ROWB 272          // padded smem row (128 bf16 + 8 pad)
#define WREG (32 * ROWB)  // per-warp A region = 8704 B

typedef uint32_t u32;

// ---------------- device scratch (no allocs allowed) ----------------
__device__ float g_CKp[KCOMP];
__device__ float g_LDR[NCLS];
__device__ __nv_bfloat16 g_B[NCOLS * KDIM];
__device__ float g_blockCe[8192];
__device__ int   g_blockCnt[8192];
__device__ unsigned int g_done;
__device__ unsigned int g_chunk;

// ---------------- smem layout (bytes) ----------------
#define A_OFF    0                    // 12 x 8704 = 104448
#define B_OFF    104448               // 240 x 272 = 65280
#define CKP_OFF  169728               // 96 floats
#define LDR_OFF  170112               // 24 floats
#define SMEM_TOTAL 170240

// ---------------- PTX helpers ----------------
__device__ __forceinline__ u32 smem_u32(const void* p) {
    u32 a;
    asm("{ .reg .u64 t; cvta.to.shared.u64 t, %1; cvt.u32.u64 %0, t; }"
        : "=r"(a) : "l"(p));
    return a;
}
#define LDMX4(r, a) \
    asm volatile("ldmatrix.sync.aligned.m8n8.x4.shared.b16 {%0,%1,%2,%3}, [%4];" \
        : "=r"((r)[0]), "=r"((r)[1]), "=r"((r)[2]), "=r"((r)[3]) : "r"(a))
#define LDMX2(r0, r1, a) \
    asm volatile("ldmatrix.sync.aligned.m8n8.x2.shared.b16 {%0,%1}, [%2];" \
        : "=r"(r0), "=r"(r1) : "r"(a))
#define MMA(c, a, b0_, b1_) \
    asm volatile("mma.sync.aligned.m16n8k16.row.col.f32.bf16.bf16.f32 " \
        "{%0,%1,%2,%3}, {%4,%5,%6,%7}, {%8,%9}, {%0,%1,%2,%3};" \
        : "+f"((c)[0]), "+f"((c)[1]), "+f"((c)[2]), "+f"((c)[3]) \
        : "r"((a)[0]), "r"((a)[1]), "r"((a)[2]), "r"((a)[3]), "r"(b0_), "r"(b1_))

__device__ __forceinline__ u32 pkbf(float lo, float hi) {
    return (u32)__bfloat16_as_ushort(__float2bfloat16_rn(lo)) |
           ((u32)__bfloat16_as_ushort(__float2bfloat16_rn(hi)) << 16);
}

// B column index for (class c, slot s): pass P = c>>2, quad-pos tg = c&3,
// n-tile t6 = s>>1, parity = s&1 -> n = P*48 + t6*8 + 2*tg + parity
__device__ __forceinline__ int bcol(int c, int s) {
    return (c >> 2) * 48 + (s >> 1) * 8 + 2 * (c & 3) + (s & 1);
}

// ---------------- prep (fused): constants + permuted B matrix --------
__global__ __launch_bounds__(64) void prep_kernel(
        const float* __restrict__ cov,
        const float* __restrict__ mean,
        const float* __restrict__ tmem,
        const float* __restrict__ ct,
        const float* __restrict__ cs) {
    __shared__ float red[64], red2[64];
    const int t = threadIdx.x;
    const int bk = blockIdx.x;
    const __nv_bfloat16 z = __float2bfloat16_rn(0.f);

    if (bk < KCOMP) {
        const int c = bk / 5, j = bk - 5 * c;
        const float s = cov[bk * AF + t];
        const float l = mean[bk * AF + t];
        const float q = 1.0f / (s * s);
        const int n1 = bcol(c, j) * KDIM;        // maha slot j: [ql | -0.5q]
        const int n2 = bcol(c, 5 + j) * KDIM;    // l slot:      [l  | 0]
        g_B[n1 + t]      = __float2bfloat16_rn(l * q);
        g_B[n1 + 64 + t] = __float2bfloat16_rn(-0.5f * q);
        g_B[n2 + t]      = __float2bfloat16_rn(l);
        g_B[n2 + 64 + t] = z;
        red [t] = logf(s);
        red2[t] = l * l * q;
        __syncthreads();
        #pragma unroll
        for (int st = 32; st > 0; st >>= 1) {
            if (t < st) { red[t] += red[t + st]; red2[t] += red2[t + st]; }
            __syncthreads();
        }
        if (t == 0)
            g_CKp[bk] = -0.5f * (AF * LOG2PI_F + 2.f * red[0] + red2[0]);
    } else if (bk < KCOMP + NCLS) {
        const int c = bk - KCOMP;
        const float* p = tmem + ((size_t)(c * AF + t)) * 100;
        float s = 0.f;
        for (int i = 0; i < 100; i++) s += p[i];
        s *= 0.01f;
        red[t] = s * s;
        __syncthreads();
        #pragma unroll
        for (int st = 32; st > 0; st >>= 1) {
            if (t < st) red[t] += red[t + st];
            __syncthreads();
        }
        const float n = fmaxf(sqrtf(red[0]), 1e-12f);
        const int n1 = bcol(c, 10) * KDIM;       // mt slot
        const int n2 = bcol(c, 11) * KDIM;       // pad slot
        g_B[n1 + t]      = __float2bfloat16_rn(s / n);
        g_B[n1 + 64 + t] = z;
        g_B[n2 + t]      = z;
        g_B[n2 + 64 + t] = z;
        if (t == 0) {
            float r = ct[c] / cs[c];
            if (isnan(r)) r = 0.f;
            g_LDR[c] = logf(r);
        }
    } else {
        // zero the 12 columns of the missing class 19 (pass 4, tg 3)
        #pragma unroll
        for (int s = 0; s < 12; s++) {
            const int n = bcol(19, s) * KDIM;
            g_B[n + t]      = z;
            g_B[n + 64 + t] = z;
        }
        if (t == 0) { g_done = 0; g_chunk = 0; }
    }
}

// ---------------- main: warp-independent chunks, lane-local epilogue -
__global__ __launch_bounds__(TPB, 1) void main_kernel(
        const float* __restrict__ feat,
        const int*   __restrict__ mask,
        float* __restrict__ out,
        int nchunks) {
    extern __shared__ char smem[];
    const u32 sb = smem_u32(smem);
    float* sCKp = (float*)(smem + CKP_OFF);
    float* sLDR = (float*)(smem + LDR_OFF);

    const int tid = threadIdx.x;
    const int lane = tid & 31;
    const int w = tid >> 5;
    const int tg = lane & 3;           // quad position = class offset

    // ---- one-time: B -> smem (rows padded to 272B), single copy
    for (int i = tid; i < NCOLS * 16; i += TPB) {
        const int row = i >> 4, u = i & 15;
        *(uint4*)(smem + B_OFF + row * ROWB + u * 16) =
            ((const uint4*)g_B)[row * 16 + u];
    }
    if (tid < KCOMP) sCKp[tid] = g_CKp[tid];
    if (tid < NCLS)  sLDR[tid] = g_LDR[tid];
    __syncthreads();

    // ---- ldmatrix lane address bases (within this warp's A region)
    const u32 wbase = sb + A_OFF + (u32)w * WREG;
    u32 aAddr[2];
    {
        const int rin = (lane & 7) + ((lane >> 3) & 1) * 8;
        const int k16 = (lane >> 4) & 1;
        aAddr[0] = wbase + (u32)rin * ROWB + k16 * 16;
        aAddr[1] = aAddr[0] + 16 * ROWB;
    }
    const u32 bA4 = sb + B_OFF
        + (u32)((lane & 7) + ((lane >> 4) & 1) * 8) * ROWB
        + ((lane >> 3) & 1) * 16;
    const int m15 = lane & 15;
    const u32 bA2 = sb + B_OFF + (u32)(16 + (m15 & 7)) * ROWB
        + ((m15 >> 3) & 1) * 16;

    // ---- warp-independent dynamic chunk loop
    for (;;) {
        unsigned int ck;
        if (lane == 0) ck = atomicAdd(&g_chunk, 1u);
        ck = __shfl_sync(0xffffffffu, ck, 0);
        if (ck >= (unsigned int)nchunks) break;

        const int pix = (int)ck * 32 + lane;
        const int hw = pix & 65535;
        const int b = pix >> 16;

        // ---- validity: some non-ignore class with count >= 12 in 4x4 block
        const int ww = pix & (WF - 1);
        const int hh = (pix >> 8) & (WF - 1);
        const int* mb = mask + ((size_t)b << 20) + (size_t)(hh << 2) * 1024 + (ww << 2);
        int valid = 0;
        {
            int lab[16];
            #pragma unroll
            for (int r = 0; r < 4; r++) {
                int4 v4 = *(const int4*)(mb + (size_t)r * 1024);
                lab[r * 4 + 0] = v4.x; lab[r * 4 + 1] = v4.y;
                lab[r * 4 + 2] = v4.z; lab[r * 4 + 3] = v4.w;
            }
            #pragma unroll
            for (int i = 0; i < 5; i++) {
                int cnt = 0;
                #pragma unroll
                for (int j = 0; j < 16; j++) cnt += (lab[j] == lab[i]);
                if (lab[i] != 255 && cnt >= 12) valid = 1;
            }
        }

        // ---- load feature (coalesced within warp), normalize in fp32
        const float* fbp = feat + ((size_t)b << 22) + hw;
        float x[AF];
        float n0 = 0.f, n1 = 0.f, n2 = 0.f, n3 = 0.f;
        #pragma unroll
        for (int a = 0; a < AF; a += 4) {
            x[a]     = fbp[(size_t)a << 16];
            x[a + 1] = fbp[(size_t)(a + 1) << 16];
            x[a + 2] = fbp[(size_t)(a + 2) << 16];
            x[a + 3] = fbp[(size_t)(a + 3) << 16];
            n0 = fmaf(x[a], x[a], n0);         n1 = fmaf(x[a + 1], x[a + 1], n1);
            n2 = fmaf(x[a + 2], x[a + 2], n2); n3 = fmaf(x[a + 3], x[a + 3], n3);
        }
        const float inv = 1.0f / fmaxf(sqrtf((n0 + n1) + (n2 + n3)), 1e-12f);

        // ---- write A row lane = [x_hat | x_hat^2] bf16 (warp-local)
        __syncwarp();
        {
            char* arow = smem + A_OFF + (size_t)w * WREG + (size_t)lane * ROWB;
            #pragma unroll
            for (int i = 0; i < 8; i++) {
                const int a = i * 8;
                float e0 = x[a] * inv,     e1 = x[a + 1] * inv;
                float e2 = x[a + 2] * inv, e3 = x[a + 3] * inv;
                float e4 = x[a + 4] * inv, e5 = x[a + 5] * inv;
                float e6 = x[a + 6] * inv, e7 = x[a + 7] * inv;
                uint4 v0, v1;
                v0.x = pkbf(e0, e1); v0.y = pkbf(e2, e3);
                v0.z = pkbf(e4, e5); v0.w = pkbf(e6, e7);
                v1.x = pkbf(e0 * e0, e1 * e1); v1.y = pkbf(e2 * e2, e3 * e3);
                v1.z = pkbf(e4 * e4, e5 * e5); v1.w = pkbf(e6 * e6, e7 * e7);
                ((uint4*)arow)[i] = v0;
                ((uint4*)arow)[8 + i] = v1;
            }
        }
        __syncwarp();

        // ---- resident A fragments (warp's 32 rows x K=128)
        u32 af[2][8][4];
        #pragma unroll
        for (int mt = 0; mt < 2; mt++)
            #pragma unroll
            for (int ks = 0; ks < 8; ks++)
                LDMX4(af[mt][ks], aAddr[mt] + ks * 32);

        // ---- per-row streaming state (rows: g, g+8, g+16, g+24)
        float gm[4]    = {-1e30f, -1e30f, -1e30f, -1e30f};
        float Zs[4]    = {0.f, 0.f, 0.f, 0.f};
        float bestL[4] = {-1e30f, -1e30f, -1e30f, -1e30f};
        float glab[4]  = {0.f, 0.f, 0.f, 0.f};
        float mlse[4], lmaxc[4];

        // ---- 10 sub-passes of 24 cols (2 per class-group pass)
        #pragma unroll 1
        for (int sp = 0; sp < NSUB; sp++) {
            const int P = sp >> 1, sub = sp & 1;
            const int c = 4 * P + tg;              // this lane's class
            const int cvalid = (c < NCLS);

            float cacc[24];
            #pragma unroll
            for (int i = 0; i < 24; i++) cacc[i] = 0.f;
            const u32 b4 = bA4 + (u32)sp * (24 * ROWB);
            const u32 b2 = bA2 + (u32)sp * (24 * ROWB);

            u32 br[4], d0, d1;
            LDMX4(br, b4);
            LDMX2(d0, d1, b2);
            #pragma unroll
            for (int ks = 0; ks < 8; ks++) {
                u32 brn[4], dn0, dn1;
                if (ks < 7) {
                    LDMX4(brn, b4 + (ks + 1) * 32);
                    LDMX2(dn0, dn1, b2 + (ks + 1) * 32);
                }
                MMA(cacc + 0,  af[0][ks], br[0], br[1]);
                MMA(cacc + 4,  af[1][ks], br[0], br[1]);
                MMA(cacc + 8,  af[0][ks], br[2], br[3]);
                MMA(cacc + 12, af[1][ks], br[2], br[3]);
                MMA(cacc + 16, af[0][ks], d0, d1);
                MMA(cacc + 20, af[1][ks], d0, d1);
                if (ks < 7) {
                    br[0] = brn[0]; br[1] = brn[1]; br[2] = brn[2]; br[3] = brn[3];
                    d0 = dn0; d1 = dn1;
                }
            }
            // accum layout: cacc[nt*8 + mt*4 + i]; per row r (0..3):
            // o = ((r&1)<<1) + ((r>>1)<<2) selects (c0,c1)/(c2,c3) x mt

            if (sub == 0) {
                // slots 0..5 = maha m0..4, l m0  -> finish lse, carry l-max
                float ck0 = 0.f, ck1 = 0.f, ck2 = 0.f, ck3 = 0.f, ck4 = 0.f;
                if (cvalid) {
                    ck0 = sCKp[c * 5 + 0]; ck1 = sCKp[c * 5 + 1];
                    ck2 = sCKp[c * 5 + 2]; ck3 = sCKp[c * 5 + 3];
                    ck4 = sCKp[c * 5 + 4];
                }
                #pragma unroll
                for (int r = 0; r < 4; r++) {
                    const int o = ((r & 1) << 1) + ((r >> 1) << 2);
                    const float m0 = cacc[o]      + ck0;
                    const float m1 = cacc[o + 1]  + ck1;
                    const float m2 = cacc[8 + o]  + ck2;
                    const float m3 = cacc[8 + o + 1] + ck3;
                    const float m4 = cacc[16 + o] + ck4;
                    lmaxc[r] = cacc[16 + o + 1];
                    float mm = fmaxf(fmaxf(fmaxf(m0, m1), fmaxf(m2, m3)), m4);
                    float ms = __expf(m0 - mm) + __expf(m1 - mm) + __expf(m2 - mm)
                             + __expf(m3 - mm) + __expf(m4 - mm);
                    mlse[r] = mm + __logf(ms);
                }
            } else {
                // slots 6..11 = l m1..4, mt, pad -> finish class, stream update
                const float ldr = cvalid ? sLDR[c] : 0.f;
                #pragma unroll
                for (int r = 0; r < 4; r++) {
                    const int o = ((r & 1) << 1) + ((r >> 1) << 2);
                    float lx = fmaxf(fmaxf(fmaxf(cacc[o], cacc[o + 1]),
                                           fmaxf(cacc[8 + o], cacc[8 + o + 1])),
                                     lmaxc[r]);
                    const float simlog = cacc[16 + o];
                    const float L = ldr + simlog + mlse[r];
                    const float g = lx * 0.01f;
                    if (cvalid) {
                        if (g > gm[r]) { Zs[r] = Zs[r] * __expf(gm[r] - g) + 1.f; gm[r] = g; }
                        else           { Zs[r] += __expf(g - gm[r]); }
                        if (L > bestL[r]) { bestL[r] = L; glab[r] = g; }
                    }
                }
            }
        }

        // ---- quad combine (classes are split across the 4 quad lanes)
        float ceSum = 0.f;
        int cntSum = 0;
        const int g0 = lane >> 2;
        #pragma unroll
        for (int r = 0; r < 4; r++) {
            float gmv = gm[r], Zv = Zs[r], bL = bestL[r], gl = glab[r];
            #pragma unroll
            for (int off = 1; off <= 2; off <<= 1) {
                const float og  = __shfl_xor_sync(0xffffffffu, gmv, off);
                const float oZ  = __shfl_xor_sync(0xffffffffu, Zv, off);
                const float ob  = __shfl_xor_sync(0xffffffffu, bL, off);
                const float ogl = __shfl_xor_sync(0xffffffffu, gl, off);
                const float nm = fmaxf(gmv, og);
                Zv = Zv * __expf(gmv - nm) + oZ * __expf(og - nm);
                gmv = nm;
                if (ob > bL) { bL = ob; gl = ogl; }
            }
            const int row = g0 + r * 8;
            const int vr = __shfl_sync(0xffffffffu, valid, row);
            ceSum += vr ? (gmv + __logf(Zv) - gl) : 0.f;
            cntSum += vr;
        }
        if (tg != 0) { ceSum = 0.f; cntSum = 0; }   // one contribution per pixel

        // deterministic warp butterfly reduction -> per-chunk partial
        #pragma unroll
        for (int off = 16; off > 0; off >>= 1) {
            ceSum  += __shfl_xor_sync(0xffffffffu, ceSum, off);
            cntSum += __shfl_xor_sync(0xffffffffu, cntSum, off);
        }
        if (lane == 0) {
            g_blockCe[ck]  = ceSum;
            g_blockCnt[ck] = cntSum;
        }
    }

    // ---- fused finalize: last CTA reduces all per-chunk partials
    __shared__ bool isLast;
    __shared__ float sfw[NWARP];
    __shared__ int   siw[NWARP];
    __threadfence();
    __syncthreads();
    if (tid == 0) {
        unsigned int o = atomicAdd(&g_done, 1u);
        isLast = (o == (unsigned int)(gridDim.x - 1));
    }
    __syncthreads();
    if (isLast) {
        __threadfence();
        float s = 0.f; int c = 0;
        for (int i = tid; i < nchunks; i += TPB) {
            s += g_blockCe[i];
            c += g_blockCnt[i];
        }
        #pragma unroll
        for (int off = 16; off > 0; off >>= 1) {
            s += __shfl_xor_sync(0xffffffffu, s, off);
            c += __shfl_xor_sync(0xffffffffu, c, off);
        }
        if (lane == 0) { sfw[w] = s; siw[w] = c; }
        __syncthreads();
        if (tid == 0) {
            float tot = 0.f; int cnt = 0;
            #pragma unroll
            for (int i = 0; i < NWARP; i++) { tot += sfw[i]; cnt += siw[i]; }
            out[0] = tot / fmaxf((float)cnt, 1.0f);
        }
    }
}

// ---------------- launch ----------------
extern "C" void kernel_launch(void* const* d_in, const int* in_sizes, int n_in,
                              void* d_out, int out_size) {
    const float* feat = (const float*)d_in[0];
    const int*   mask = (const int*)d_in[1];
    const float* mean = (const float*)d_in[2];
    const float* cov  = (const float*)d_in[3];
    const float* tmem = (const float*)d_in[4];
    const float* ct   = (const float*)d_in[5];
    const float* cs   = (const float*)d_in[6];

    const int B = in_sizes[0] / (AF * HF * WF);
    const int npix = B * HF * WF;
    const int nchunks = npix / 32;

    cudaFuncSetAttribute(main_kernel,
                         cudaFuncAttributeMaxDynamicSharedMemorySize, SMEM_TOTAL);

    prep_kernel<<<KCOMP + NCLS + 1, 64>>>(cov, mean, tmem, ct, cs);
    main_kernel<<<148, TPB, SMEM_TOTAL>>>(feat, mask, (float*)d_out, nchunks);
}